// round 4
// baseline (speedup 1.0000x reference)
#include <cuda_runtime.h>
#include <cstdint>

#define M_TOTAL (64 * 2048)   // 131072 rows
#define KDIM 128
#define HID 256
#define NPACK 768             // i,g,o gates only (f-gate dead: c_prev == 0)
#define BM 128
#define NGRP 4
#define CTAS_PER_GRP 256
#define ITERS 4
#define NTHREADS 512

#define BIAS_OFF 0
#define B_OFF 192
#define B_FLOATS (8 * 3 * 16 * 64)            // 24576 floats = 96KB per group
#define A0_OFF (B_OFF + B_FLOATS)             // 24768
#define A_FLOATS (BM * KDIM)                  // 16384 (64KB, swizzled, no pad)
#define A1_OFF (A0_OFF + A_FLOATS)
#define SMEM_FLOATS (A1_OFF + A_FLOATS)       // 57536
#define SMEM_BYTES (SMEM_FLOATS * 4)          // 230144 B

// ---------------- device scratch ----------------
// B fragments: [grp 4][jf 8][gate 3][ks 16][lane 32][2], tf32-rounded.
__device__ float g_Wp[NGRP * B_FLOATS];
__device__ float g_bias[NGRP * 192];   // [grp][gate 3][64]

__device__ __forceinline__ float to_tf32(float v) {
    uint32_t r;
    asm("cvt.rna.tf32.f32 %0, %1;" : "=r"(r) : "f"(v));
    return __uint_as_float(r);
}

__global__ void prep_kernel(const float* __restrict__ W_ih,
                            const float* __restrict__ b_ih,
                            const float* __restrict__ b_hh) {
    int d = blockIdx.x * blockDim.x + threadIdx.x;
    if (d < NGRP * 192) {
        int grp = d / 192, r = d % 192;
        int gate = r / 64, jl = r % 64;
        int src = (gate == 0 ? 0 : (gate == 1 ? 512 : 768)) + grp * 64 + jl;
        g_bias[d] = b_ih[src] + b_hh[src];
    }
    if (d >= NPACK * KDIM) return;
    int grp = d / B_FLOATS;          int r1 = d % B_FLOATS;
    int jf  = r1 / 3072;             int r2 = r1 % 3072;
    int gate = r2 / 1024;            int r3 = r2 % 1024;
    int ks  = r3 / 64;               int r4 = r3 % 64;
    int lane = r4 >> 1;              int b01 = r4 & 1;
    int gid = lane >> 2, tig = lane & 3;
    // m16n8k8.row.col B frag: b0 = B[k=tig][n=gid], b1 = B[k=tig+4][n=gid]
    int j_global = grp * 64 + jf * 8 + gid;
    int k = ks * 8 + tig + b01 * 4;
    int src_row = (gate == 0 ? 0 : (gate == 1 ? 512 : 768)) + j_global;
    g_Wp[d] = to_tf32(W_ih[src_row * KDIM + k]);
}

__device__ __forceinline__ void mma_tf32(float (&dacc)[4], const uint32_t (&a)[4],
                                         const uint32_t (&b)[2]) {
    asm volatile(
        "mma.sync.aligned.m16n8k8.row.col.f32.tf32.tf32.f32 "
        "{%0,%1,%2,%3}, {%4,%5,%6,%7}, {%8,%9}, {%0,%1,%2,%3};"
        : "+f"(dacc[0]), "+f"(dacc[1]), "+f"(dacc[2]), "+f"(dacc[3])
        : "r"(a[0]), "r"(a[1]), "r"(a[2]), "r"(a[3]), "r"(b[0]), "r"(b[1]));
}

__device__ __forceinline__ float tanh_ap(float x) {
    float y;
    asm("tanh.approx.f32 %0, %1;" : "=f"(y) : "f"(x));
    return y;
}
__device__ __forceinline__ float sig_ap(float x) {
    return fmaf(0.5f, tanh_ap(0.5f * x), 0.5f);
}

// Store a prefetched x tile into XOR-swizzled A smem (tf32-rounded).
// word(row, col) = row*128 + (col ^ ((row&7)*4)); float4 at kq -> kq ^ (row&7).
__device__ __forceinline__ void store_a_tile(float* As, const float4* pref, int tid) {
#pragma unroll
    for (int i = 0; i < 8; ++i) {
        int idx = i * NTHREADS + tid;
        int m = idx >> 5, kq = idx & 31;
        float4 v = pref[i];
        v.x = to_tf32(v.x); v.y = to_tf32(v.y);
        v.z = to_tf32(v.z); v.w = to_tf32(v.w);
        *(float4*)(As + m * KDIM + 4 * (kq ^ (m & 7))) = v;
    }
}

__global__ __launch_bounds__(NTHREADS, 1)
void lstm_mma_kernel(const float* __restrict__ x, float* __restrict__ out) {
    extern __shared__ float sm[];
    float* bias_s = sm + BIAS_OFF;
    float* Bs = sm + B_OFF;

    const int tid = threadIdx.x;
    const int lane = tid & 31;
    const int wid = tid >> 5;
    const int gid = lane >> 2;
    const int tig = lane & 3;
    const int wm = wid & 3;        // 4 m-warps * 32 rows
    const int wj = wid >> 2;       // 4 j-warps * 2 jf (16 cols) * 3 gates
    const int grp = blockIdx.x & 3;
    const int cta_m = blockIdx.x >> 2;

    if (tid < 192) bias_s[tid] = g_bias[grp * 192 + tid];
    {   // B fragments for this group: 96KB linear copy
        const float4* Bg = (const float4*)(g_Wp + (size_t)grp * B_FLOATS);
        float4* Bd = (float4*)Bs;
#pragma unroll
        for (int i = 0; i < 12; ++i) Bd[i * NTHREADS + tid] = Bg[i * NTHREADS + tid];
    }
    {   // first A tile
        const float4* src = (const float4*)(x + (size_t)(cta_m * BM) * KDIM);
        float4 pref[8];
#pragma unroll
        for (int i = 0; i < 8; ++i) pref[i] = src[i * NTHREADS + tid];
        store_a_tile(sm + A0_OFF, pref, tid);
    }
    __syncthreads();

    const int rb0 = wm * 32;                // warp row base
    const int jf0 = wj * 2;                 // first jf of this warp

    for (int it = 0; it < ITERS; ++it) {
        float* As = sm + ((it & 1) ? A1_OFF : A0_OFF);
        float acc[2][2][3][4];
#pragma unroll
        for (int mt = 0; mt < 2; ++mt)
#pragma unroll
            for (int jf = 0; jf < 2; ++jf)
#pragma unroll
                for (int g = 0; g < 3; ++g)
#pragma unroll
                    for (int q = 0; q < 4; ++q) acc[mt][jf][g][q] = 0.0f;

#pragma unroll
        for (int ks = 0; ks < 16; ++ks) {
            const int w0 = (ks * 8 + tig) ^ (gid * 4);
            const int w4 = (ks * 8 + tig + 4) ^ (gid * 4);
            uint32_t a[2][4];
#pragma unroll
            for (int mt = 0; mt < 2; ++mt) {
                const float* ar = As + (rb0 + mt * 16 + gid) * KDIM;
                a[mt][0] = __float_as_uint(ar[w0]);
                a[mt][1] = __float_as_uint(ar[8 * KDIM + w0]);
                a[mt][2] = __float_as_uint(ar[w4]);
                a[mt][3] = __float_as_uint(ar[8 * KDIM + w4]);
            }
#pragma unroll
            for (int jf = 0; jf < 2; ++jf)
#pragma unroll
                for (int g = 0; g < 3; ++g) {
                    const float* bp = Bs + ((((jf0 + jf) * 3 + g) * 16) + ks) * 64
                                    + lane * 2;
                    uint32_t b[2] = { __float_as_uint(bp[0]), __float_as_uint(bp[1]) };
#pragma unroll
                    for (int mt = 0; mt < 2; ++mt)
                        mma_tf32(acc[mt][jf][g], a[mt], b);
                }
        }

        const bool more = (it + 1 < ITERS);
        float4 pref[8];
        if (more) {   // LDG next tile now; epilogue hides the DRAM latency
            const float4* src = (const float4*)
                (x + (size_t)((cta_m + (it + 1) * CTAS_PER_GRP) * BM) * KDIM);
#pragma unroll
            for (int i = 0; i < 8; ++i) pref[i] = src[i * NTHREADS + tid];
        }

        // Epilogue: i/g/o for the same (m,j) live in this thread's accs.
        const int bm = (cta_m + it * CTAS_PER_GRP) * BM;
#pragma unroll
        for (int jf = 0; jf < 2; ++jf) {
            const int jl = (jf0 + jf) * 8 + 2 * tig;
            const float2 bi = *(const float2*)(bias_s + jl);
            const float2 bg = *(const float2*)(bias_s + 64 + jl);
            const float2 bo = *(const float2*)(bias_s + 128 + jl);
            const int jcol = grp * 64 + jl;
#pragma unroll
            for (int mt = 0; mt < 2; ++mt) {
                const int m0 = bm + rb0 + mt * 16 + gid;
#pragma unroll
                for (int rr = 0; rr < 2; ++rr) {
                    float i0 = sig_ap(acc[mt][jf][0][rr * 2 + 0] + bi.x);
                    float i1 = sig_ap(acc[mt][jf][0][rr * 2 + 1] + bi.y);
                    float g0 = tanh_ap(acc[mt][jf][1][rr * 2 + 0] + bg.x);
                    float g1 = tanh_ap(acc[mt][jf][1][rr * 2 + 1] + bg.y);
                    float o0 = sig_ap(acc[mt][jf][2][rr * 2 + 0] + bo.x);
                    float o1 = sig_ap(acc[mt][jf][2][rr * 2 + 1] + bo.y);
                    float c0 = i0 * g0, c1 = i1 * g1;
                    float h0 = o0 * tanh_ap(c0), h1 = o1 * tanh_ap(c1);
                    size_t off = (size_t)(m0 + rr * 8) * HID + jcol;
                    *(float2*)(out + off) = make_float2(h0, h1);
                    *(float2*)(out + (size_t)M_TOTAL * HID + off) = make_float2(c0, c1);
                }
            }
        }

        if (more) {   // write next tile into the other buffer
            store_a_tile(sm + ((it & 1) ? A0_OFF : A1_OFF), pref, tid);
            __syncthreads();
        }
    }
}

extern "C" void kernel_launch(void* const* d_in, const int* in_sizes, int n_in,
                              void* d_out, int out_size) {
    const float* x    = (const float*)d_in[0];
    const float* W_ih = (const float*)d_in[1];
    // d_in[2] = W_hh unused (h_prev == 0 in reference)
    const float* b_ih = (const float*)d_in[3];
    const float* b_hh = (const float*)d_in[4];
    float* out = (float*)d_out;

    cudaFuncSetAttribute(lstm_mma_kernel,
                         cudaFuncAttributeMaxDynamicSharedMemorySize, SMEM_BYTES);

    prep_kernel<<<(NPACK * KDIM + 255) / 256, 256>>>(W_ih, b_ih, b_hh);
    lstm_mma_kernel<<<NGRP * CTAS_PER_GRP, NTHREADS, SMEM_BYTES>>>(x, out);
}

// round 6
// speedup vs baseline: 1.6298x; 1.6298x over previous
#include <cuda_runtime.h>
#include <cuda_fp16.h>
#include <cstdint>

#define M_TOTAL (64 * 2048)   // 131072 rows
#define KDIM 128
#define HID 256
#define NPACK 768             // i,g,o gates only (f-gate dead: c_prev == 0)
#define BM 128
#define NGRP 4
#define CTAS_PER_GRP 256
#define ITERS 4
#define NTHREADS 512

// SMEM layout (bytes)
#define BIAS_OFF 0                       // 192 floats = 768B
#define B_OFF 1024                       // 48KB: fp16 B fragments
#define B_BYTES (8 * 3 * 8 * 32 * 8)     // jf*gate*ks*lane*8B = 49152
#define A0_OFF (B_OFF + B_BYTES)         // 50176
#define A_BYTES (BM * KDIM * 2)          // 32768 (fp16, swizzled)
#define A1_OFF (A0_OFF + A_BYTES)
#define SMEM_BYTES (A1_OFF + A_BYTES)    // 115712

// ---------------- device scratch ----------------
// B fp16 fragments: [grp 4][jf 8][gate 3][ks 8][lane 32][b0.lo,b0.hi,b1.lo,b1.hi]
__device__ __half g_Wp[NGRP * (B_BYTES / 2)];
__device__ float g_bias[NGRP * 192];   // [grp][gate 3][64]

__global__ void prep_kernel(const float* __restrict__ W_ih,
                            const float* __restrict__ b_ih,
                            const float* __restrict__ b_hh) {
    int d = blockIdx.x * blockDim.x + threadIdx.x;
    if (d < NGRP * 192) {
        int grp = d / 192, r = d % 192;
        int gate = r / 64, jl = r % 64;
        int src = (gate == 0 ? 0 : (gate == 1 ? 512 : 768)) + grp * 64 + jl;
        g_bias[d] = b_ih[src] + b_hh[src];
    }
    if (d >= NPACK * KDIM) return;
    // decompose into fp16 B-frag coords (24576 halves per group)
    int grp = d / 24576;          int r1 = d % 24576;
    int jf  = r1 / 3072;          int r2 = r1 % 3072;
    int gate = r2 / 1024;         int r3 = r2 % 1024;
    int ks  = r3 / 128;           int r4 = r3 % 128;
    int lane = r4 >> 2;           int rr = r4 & 3;
    int pair = rr >> 1;           int half = rr & 1;
    int gid = lane >> 2, tig = lane & 3;
    // m16n8k16.row.col B frag: b0 = B[k=2tig(+1)][n=gid], b1 = B[k=2tig+8(+9)][n=gid]
    int k = ks * 16 + pair * 8 + 2 * tig + half;
    int j_global = grp * 64 + jf * 8 + gid;
    int src_row = (gate == 0 ? 0 : (gate == 1 ? 512 : 768)) + j_global;
    g_Wp[d] = __float2half_rn(W_ih[src_row * KDIM + k]);
}

// ---------------- helpers ----------------
__device__ __forceinline__ uint32_t smem_u32(const void* p) {
    uint32_t a;
    asm("{ .reg .u64 t; cvta.to.shared.u64 t, %1; cvt.u32.u64 %0, t; }" : "=r"(a) : "l"(p));
    return a;
}

// Pack two f32 into one f16x2 register (lo = a, hi = b).
__device__ __forceinline__ uint32_t pack_f16x2(float a, float b) {
    uint32_t r;
    asm("cvt.rn.f16x2.f32 %0, %1, %2;" : "=r"(r) : "f"(b), "f"(a));
    return r;
}

__device__ __forceinline__ void mma_f16(float (&dacc)[4], const uint32_t (&a)[4],
                                        const uint32_t (&b)[2]) {
    asm volatile(
        "mma.sync.aligned.m16n8k16.row.col.f32.f16.f16.f32 "
        "{%0,%1,%2,%3}, {%4,%5,%6,%7}, {%8,%9}, {%0,%1,%2,%3};"
        : "+f"(dacc[0]), "+f"(dacc[1]), "+f"(dacc[2]), "+f"(dacc[3])
        : "r"(a[0]), "r"(a[1]), "r"(a[2]), "r"(a[3]), "r"(b[0]), "r"(b[1]));
}

__device__ __forceinline__ void ldsm_x4(uint32_t (&a)[4], uint32_t addr) {
    asm volatile("ldmatrix.sync.aligned.m8n8.x4.shared.b16 {%0,%1,%2,%3}, [%4];"
                 : "=r"(a[0]), "=r"(a[1]), "=r"(a[2]), "=r"(a[3]) : "r"(addr));
}

__device__ __forceinline__ float tanh_ap(float x) {
    float y;
    asm("tanh.approx.f32 %0, %1;" : "=f"(y) : "f"(x));
    return y;
}
__device__ __forceinline__ float sig_ap(float x) {
    return fmaf(0.5f, tanh_ap(0.5f * x), 0.5f);
}

// Store prefetched x tile into XOR-swizzled fp16 A smem.
// Row = 256B (16 chunks of 16B); chunk q at row m -> q ^ (m&7).
__device__ __forceinline__ void store_a_tile(char* As, const float4* pref, int tid) {
#pragma unroll
    for (int i = 0; i < 8; ++i) {
        int idx = i * NTHREADS + tid;      // 0..4095 (units of 4 floats -> 8B fp16)
        int m = idx >> 5, kq = idx & 31;   // kq: 8B sub-chunk in row
        float4 v = pref[i];
        uint2 hv;
        hv.x = pack_f16x2(v.x, v.y);
        hv.y = pack_f16x2(v.z, v.w);
        int q = kq >> 1, sub = kq & 1;
        *(uint2*)(As + m * 256 + ((q ^ (m & 7)) << 4) + sub * 8) = hv;
    }
}

__global__ __launch_bounds__(NTHREADS, 1)
void lstm_mma_kernel(const float* __restrict__ x, float* __restrict__ out) {
    extern __shared__ char smc[];
    float* bias_s = (float*)(smc + BIAS_OFF);
    char* Bs = smc + B_OFF;

    const int tid = threadIdx.x;
    const int lane = tid & 31;
    const int wid = tid >> 5;
    const int gid = lane >> 2;
    const int tig = lane & 3;
    const int wm = wid & 3;        // 4 m-warps * 32 rows
    const int wj = wid >> 2;       // 4 j-warps * (2 jf * 3 gates = 48 cols)
    const int grp = blockIdx.x & 3;
    const int cta_m = blockIdx.x >> 2;

    if (tid < 192) bias_s[tid] = g_bias[grp * 192 + tid];
    {   // B fragments for this group: 48KB linear copy
        const float4* Bg = (const float4*)(g_Wp + (size_t)grp * (B_BYTES / 2));
        float4* Bd = (float4*)Bs;
#pragma unroll
        for (int i = 0; i < 6; ++i) Bd[i * NTHREADS + tid] = Bg[i * NTHREADS + tid];
    }
    {   // first A tile
        const float4* src = (const float4*)(x + (size_t)(cta_m * BM) * KDIM);
        float4 pref[8];
#pragma unroll
        for (int i = 0; i < 8; ++i) pref[i] = src[i * NTHREADS + tid];
        store_a_tile(smc + A0_OFF, pref, tid);
    }
    __syncthreads();

    const int rb0 = wm * 32;
    const int jf0 = wj * 2;
    // ldmatrix per-lane addressing (row part, constant across ks)
    const int lrow0 = rb0 + (lane & 7) + ((lane >> 3) & 1) * 8;   // mt=0 row
    const int lhi = lane >> 4;                                     // k-half select
    const uint32_t sb = smem_u32(smc);

    for (int it = 0; it < ITERS; ++it) {
        const uint32_t Au = sb + ((it & 1) ? A1_OFF : A0_OFF);
        float acc[2][2][3][4];
#pragma unroll
        for (int mt = 0; mt < 2; ++mt)
#pragma unroll
            for (int jf = 0; jf < 2; ++jf)
#pragma unroll
                for (int g = 0; g < 3; ++g)
#pragma unroll
                    for (int q = 0; q < 4; ++q) acc[mt][jf][g][q] = 0.0f;

#pragma unroll
        for (int ks = 0; ks < 8; ++ks) {
            uint32_t a[2][4];
#pragma unroll
            for (int mt = 0; mt < 2; ++mt) {
                const int row = lrow0 + mt * 16;
                const uint32_t addr = Au + row * 256
                                    + (((ks * 2 + lhi) ^ (row & 7)) << 4);
                ldsm_x4(a[mt], addr);
            }
#pragma unroll
            for (int jf = 0; jf < 2; ++jf)
#pragma unroll
                for (int g = 0; g < 3; ++g) {
                    const uint2 bv = *(const uint2*)
                        (Bs + (((((jf0 + jf) * 3 + g) * 8) + ks) * 32 + lane) * 8);
                    uint32_t b[2] = { bv.x, bv.y };
#pragma unroll
                    for (int mt = 0; mt < 2; ++mt)
                        mma_f16(acc[mt][jf][g], a[mt], b);
                }
        }

        const bool more = (it + 1 < ITERS);
        float4 pref[8];
        if (more) {   // LDG next tile; epilogue hides DRAM latency
            const float4* src = (const float4*)
                (x + (size_t)((cta_m + (it + 1) * CTAS_PER_GRP) * BM) * KDIM);
#pragma unroll
            for (int i = 0; i < 8; ++i) pref[i] = src[i * NTHREADS + tid];
        }

        // Epilogue: matching i/g/o accs live in this thread at the same (m,j).
        const int bm = (cta_m + it * CTAS_PER_GRP) * BM;
#pragma unroll
        for (int jf = 0; jf < 2; ++jf) {
            const int jl = (jf0 + jf) * 8 + 2 * tig;
            const float2 bi = *(const float2*)(bias_s + jl);
            const float2 bg = *(const float2*)(bias_s + 64 + jl);
            const float2 bo = *(const float2*)(bias_s + 128 + jl);
            const int jcol = grp * 64 + jl;
#pragma unroll
            for (int mt = 0; mt < 2; ++mt) {
                const int m0 = bm + rb0 + mt * 16 + gid;
#pragma unroll
                for (int rr = 0; rr < 2; ++rr) {
                    float i0 = sig_ap(acc[mt][jf][0][rr * 2 + 0] + bi.x);
                    float i1 = sig_ap(acc[mt][jf][0][rr * 2 + 1] + bi.y);
                    float g0 = tanh_ap(acc[mt][jf][1][rr * 2 + 0] + bg.x);
                    float g1 = tanh_ap(acc[mt][jf][1][rr * 2 + 1] + bg.y);
                    float o0 = sig_ap(acc[mt][jf][2][rr * 2 + 0] + bo.x);
                    float o1 = sig_ap(acc[mt][jf][2][rr * 2 + 1] + bo.y);
                    float c0 = i0 * g0, c1 = i1 * g1;
                    float h0 = o0 * tanh_ap(c0), h1 = o1 * tanh_ap(c1);
                    size_t off = (size_t)(m0 + rr * 8) * HID + jcol;
                    *(float2*)(out + off) = make_float2(h0, h1);
                    *(float2*)(out + (size_t)M_TOTAL * HID + off) = make_float2(c0, c1);
                }
            }
        }

        if (more) {
            __syncthreads();   // all warps finished ldmatrix on the target buffer
            store_a_tile(smc + ((it & 1) ? A0_OFF : A1_OFF), pref, tid);
            __syncthreads();
        }
    }
}

extern "C" void kernel_launch(void* const* d_in, const int* in_sizes, int n_in,
                              void* d_out, int out_size) {
    const float* x    = (const float*)d_in[0];
    const float* W_ih = (const float*)d_in[1];
    // d_in[2] = W_hh unused (h_prev == 0 in reference)
    const float* b_ih = (const float*)d_in[3];
    const float* b_hh = (const float*)d_in[4];
    float* out = (float*)d_out;

    cudaFuncSetAttribute(lstm_mma_kernel,
                         cudaFuncAttributeMaxDynamicSharedMemorySize, SMEM_BYTES);

    prep_kernel<<<(NPACK * KDIM + 255) / 256, 256>>>(W_ih, b_ih, b_hh);
    lstm_mma_kernel<<<NGRP * CTAS_PER_GRP, NTHREADS, SMEM_BYTES>>>(x, out);
}

// round 7
// speedup vs baseline: 1.7019x; 1.0442x over previous
#include <cuda_runtime.h>
#include <cuda_fp16.h>
#include <cstdint>

#define M_TOTAL (64 * 2048)   // 131072 rows
#define KDIM 128
#define HID 256
#define NPACK 768             // i,g,o gates only (f-gate dead: c_prev == 0)
#define BM 128
#define NGRP 4
#define NTHREADS 256

// SMEM layout (bytes): bias | B frags | A tile
#define BIAS_OFF 0
#define B_OFF 1024
#define B_BYTES (8 * 3 * 8 * 32 * 8)     // 49152 per group
#define A_OFF (B_OFF + B_BYTES)          // 50176
#define A_BYTES (BM * KDIM * 2)          // 32768 fp16 swizzled
#define SMEM_BYTES (A_OFF + A_BYTES)     // 82944

// ---------------- device scratch ----------------
__device__ __half g_Wp[NGRP * (B_BYTES / 2)];   // fp16 B fragments
__device__ float g_bias[NGRP * 192];            // [grp][gate 3][64]
__device__ __half g_xh[M_TOTAL * KDIM];         // x in fp16, swizzled rows (32MB)

__global__ void prep_kernel(const float* __restrict__ W_ih,
                            const float* __restrict__ b_ih,
                            const float* __restrict__ b_hh) {
    int d = blockIdx.x * blockDim.x + threadIdx.x;
    if (d < NGRP * 192) {
        int grp = d / 192, r = d % 192;
        int gate = r / 64, jl = r % 64;
        int src = (gate == 0 ? 0 : (gate == 1 ? 512 : 768)) + grp * 64 + jl;
        g_bias[d] = b_ih[src] + b_hh[src];
    }
    if (d >= NPACK * KDIM) return;
    // fp16 B-frag coords: [grp][jf 8][gate 3][ks 8][lane 32][4 halves]
    int grp = d / 24576;          int r1 = d % 24576;
    int jf  = r1 / 3072;          int r2 = r1 % 3072;
    int gate = r2 / 1024;         int r3 = r2 % 1024;
    int ks  = r3 / 128;           int r4 = r3 % 128;
    int lane = r4 >> 2;           int rr = r4 & 3;
    int pair = rr >> 1;           int half = rr & 1;
    int gid = lane >> 2, tig = lane & 3;
    int k = ks * 16 + pair * 8 + 2 * tig + half;
    int j_global = grp * 64 + jf * 8 + gid;
    int src_row = (gate == 0 ? 0 : (gate == 1 ? 512 : 768)) + j_global;
    g_Wp[d] = __float2half_rn(W_ih[src_row * KDIM + k]);
}

// Pack two f32 into f16x2 (lo = a, hi = b).
__device__ __forceinline__ uint32_t pack_f16x2(float a, float b) {
    uint32_t r;
    asm("cvt.rn.f16x2.f32 %0, %1, %2;" : "=r"(r) : "f"(b), "f"(a));
    return r;
}

// Convert x -> fp16 with the ldmatrix XOR swizzle pre-applied per 256B row.
__global__ void conv_kernel(const float* __restrict__ x) {
    int g = blockIdx.x * blockDim.x + threadIdx.x;   // one float4 each
    int row = g >> 5, kq = g & 31;
    float4 v = ((const float4*)x)[g];
    uint2 hv;
    hv.x = pack_f16x2(v.x, v.y);
    hv.y = pack_f16x2(v.z, v.w);
    int q = kq >> 1, sub = kq & 1;
    char* dst = (char*)g_xh + (size_t)row * 256 + ((q ^ (row & 7)) << 4) + sub * 8;
    *(uint2*)dst = hv;
}

// ---------------- helpers ----------------
__device__ __forceinline__ uint32_t smem_u32(const void* p) {
    uint32_t a;
    asm("{ .reg .u64 t; cvta.to.shared.u64 t, %1; cvt.u32.u64 %0, t; }" : "=r"(a) : "l"(p));
    return a;
}
__device__ __forceinline__ void cp_async16(uint32_t dst, const void* src) {
    asm volatile("cp.async.cg.shared.global [%0], [%1], 16;" :: "r"(dst), "l"(src));
}
__device__ __forceinline__ void cp_async_wait_all() {
    asm volatile("cp.async.commit_group;\ncp.async.wait_group 0;" ::: "memory");
}
__device__ __forceinline__ void mma_f16(float (&dacc)[4], const uint32_t (&a)[4],
                                        const uint32_t (&b)[2]) {
    asm volatile(
        "mma.sync.aligned.m16n8k16.row.col.f32.f16.f16.f32 "
        "{%0,%1,%2,%3}, {%4,%5,%6,%7}, {%8,%9}, {%0,%1,%2,%3};"
        : "+f"(dacc[0]), "+f"(dacc[1]), "+f"(dacc[2]), "+f"(dacc[3])
        : "r"(a[0]), "r"(a[1]), "r"(a[2]), "r"(a[3]), "r"(b[0]), "r"(b[1]));
}
__device__ __forceinline__ void ldsm_x4(uint32_t (&a)[4], uint32_t addr) {
    asm volatile("ldmatrix.sync.aligned.m8n8.x4.shared.b16 {%0,%1,%2,%3}, [%4];"
                 : "=r"(a[0]), "=r"(a[1]), "=r"(a[2]), "=r"(a[3]) : "r"(addr));
}
__device__ __forceinline__ float tanh_ap(float x) {
    float y;
    asm("tanh.approx.f32 %0, %1;" : "=f"(y) : "f"(x));
    return y;
}
__device__ __forceinline__ float sig_ap(float x) {
    return fmaf(0.5f, tanh_ap(0.5f * x), 0.5f);
}

__global__ __launch_bounds__(NTHREADS, 2)
void lstm_mma_kernel(float* __restrict__ out) {
    extern __shared__ char smc[];
    float* bias_s = (float*)(smc + BIAS_OFF);
    char* Bs = smc + B_OFF;
    const uint32_t sb = smem_u32(smc);

    const int tid = threadIdx.x;
    const int lane = tid & 31;
    const int wid = tid >> 5;
    const int gid = lane >> 2;
    const int tig = lane & 3;
    const int wm = wid & 3;        // 4 m-warps * 32 rows
    const int wj = wid >> 2;       // 2 j-warps * (4 jf * 3 gates = 96 cols)
    const int grp = blockIdx.x & 3;
    const int bm = (blockIdx.x >> 2) * BM;

    // Async loads: B frags (48KB) + A tile (32KB, pre-swizzled fp16)
    {
        const char* Bg = (const char*)g_Wp + (size_t)grp * B_BYTES;
#pragma unroll
        for (int i = 0; i < 12; ++i) {
            int c = i * NTHREADS + tid;
            cp_async16(sb + B_OFF + c * 16, Bg + c * 16);
        }
        const char* Ag = (const char*)g_xh + (size_t)bm * 256;
#pragma unroll
        for (int i = 0; i < 8; ++i) {
            int c = i * NTHREADS + tid;
            cp_async16(sb + A_OFF + c * 16, Ag + c * 16);
        }
    }
    if (tid < 192) bias_s[tid] = g_bias[grp * 192 + tid];
    cp_async_wait_all();
    __syncthreads();

    const int rb0 = wm * 32;
    const int jf0 = wj * 4;
    const int lrow0 = rb0 + (lane & 7) + ((lane >> 3) & 1) * 8;
    const int lhi = lane >> 4;
    const uint32_t Au = sb + A_OFF;

    float acc[2][4][3][4];
#pragma unroll
    for (int mf = 0; mf < 2; ++mf)
#pragma unroll
        for (int jf = 0; jf < 4; ++jf)
#pragma unroll
            for (int g = 0; g < 3; ++g)
#pragma unroll
                for (int q = 0; q < 4; ++q) acc[mf][jf][g][q] = 0.0f;

#pragma unroll
    for (int ks = 0; ks < 8; ++ks) {
        uint32_t a[2][4];
#pragma unroll
        for (int mf = 0; mf < 2; ++mf) {
            const int row = lrow0 + mf * 16;
            ldsm_x4(a[mf], Au + row * 256 + (((ks * 2 + lhi) ^ (row & 7)) << 4));
        }
#pragma unroll
        for (int jf = 0; jf < 4; ++jf)
#pragma unroll
            for (int g = 0; g < 3; ++g) {
                const uint2 bv = *(const uint2*)
                    (Bs + (((((jf0 + jf) * 3 + g) * 8) + ks) * 32 + lane) * 8);
                uint32_t b[2] = { bv.x, bv.y };
#pragma unroll
                for (int mf = 0; mf < 2; ++mf)
                    mma_f16(acc[mf][jf][g], a[mf], b);
            }
    }

    // Epilogue: matching i/g/o accs in-thread at the same (m,j).
#pragma unroll
    for (int jf = 0; jf < 4; ++jf) {
        const int jl = (jf0 + jf) * 8 + 2 * tig;
        const float2 bi = *(const float2*)(bias_s + jl);
        const float2 bg = *(const float2*)(bias_s + 64 + jl);
        const float2 bo = *(const float2*)(bias_s + 128 + jl);
        const int jcol = grp * 64 + jl;
#pragma unroll
        for (int mf = 0; mf < 2; ++mf) {
            const int m0 = bm + rb0 + mf * 16 + gid;
#pragma unroll
            for (int rr = 0; rr < 2; ++rr) {
                float i0 = sig_ap(acc[mf][jf][0][rr * 2 + 0] + bi.x);
                float i1 = sig_ap(acc[mf][jf][0][rr * 2 + 1] + bi.y);
                float g0 = tanh_ap(acc[mf][jf][1][rr * 2 + 0] + bg.x);
                float g1 = tanh_ap(acc[mf][jf][1][rr * 2 + 1] + bg.y);
                float o0 = sig_ap(acc[mf][jf][2][rr * 2 + 0] + bo.x);
                float o1 = sig_ap(acc[mf][jf][2][rr * 2 + 1] + bo.y);
                float c0 = i0 * g0, c1 = i1 * g1;
                float h0 = o0 * tanh_ap(c0), h1 = o1 * tanh_ap(c1);
                size_t off = (size_t)(m0 + rr * 8) * HID + jcol;
                *(float2*)(out + off) = make_float2(h0, h1);
                *(float2*)(out + (size_t)M_TOTAL * HID + off) = make_float2(c0, c1);
            }
        }
    }
}

extern "C" void kernel_launch(void* const* d_in, const int* in_sizes, int n_in,
                              void* d_out, int out_size) {
    const float* x    = (const float*)d_in[0];
    const float* W_ih = (const float*)d_in[1];
    // d_in[2] = W_hh unused (h_prev == 0 in reference)
    const float* b_ih = (const float*)d_in[3];
    const float* b_hh = (const float*)d_in[4];
    float* out = (float*)d_out;

    cudaFuncSetAttribute(lstm_mma_kernel,
                         cudaFuncAttributeMaxDynamicSharedMemorySize, SMEM_BYTES);

    prep_kernel<<<(NPACK * KDIM + 255) / 256, 256>>>(W_ih, b_ih, b_hh);
    conv_kernel<<<(M_TOTAL * KDIM / 4) / 512, 512>>>(x);
    lstm_mma_kernel<<<NGRP * (M_TOTAL / BM), NTHREADS, SMEM_BYTES>>>(out);
}